// round 9
// baseline (speedup 1.0000x reference)
#include <cuda_runtime.h>
#include <cuda_bf16.h>
#include <math.h>

#define NGOI 500
#define SUMH 224
#define SUMW 221
#define SUMG 56   // SUMH/4 granules

// Gene-level precomputed tables (per layer blocks).
// g_A[k]   = A_k = H_k * c_k                      (length n per gene)
// g_blg[m] = bl[4m]  granule boundary             (length n/4 per gene)
// g_fbl[m] = {bl[4m],bl[4m+1],bl[4m+2],bl[4m+3]}  (length n/4 per gene)
// g_bin[b] = {H_b, H_{b+1}, w_b, bl_b}            (length n-1 per gene)
__device__ __align__(16) float  g_A[NGOI * SUMH];     // 448 KB
__device__ __align__(16) float  g_blg[NGOI * SUMG];   // 112 KB
__device__ __align__(16) float4 g_fbl[NGOI * SUMG];   // 448 KB
__device__ __align__(16) float4 g_bin[NGOI * SUMW];   // 1.77 MB

// ---------------------------------------------------------------------------
// Precompute: one warp per (gene, layer). softmax(widths) -> w, cumsum -> bl,
// H = exp(uh), c_k = 0.5*(w_{k-1}+w_k).
// ---------------------------------------------------------------------------
__global__ void precompute_kernel(const float* __restrict__ hw,
                                  const float* __restrict__ ww,
                                  const int* __restrict__ goi)
{
    const int NB[3]   = {128, 64, 32};
    const int WOFF[3] = {0, 127, 190};
    const int HOFF[3] = {0, 128, 192};
    const int AOFF[3] = {0, NGOI * 128, NGOI * 192};
    const int GOFF[3] = {0, NGOI * 32,  NGOI * 48};
    const int BOFF[3] = {0, NGOI * 127, NGOI * 190};

    int g = blockIdx.x;
    int l = blockIdx.y;
    int lane = threadIdx.x;
    int n = NB[l];
    int E = n >> 5;
    int gid = goi[g];
    const float* uw = ww + (size_t)gid * SUMW + WOFF[l];
    const float* uh = hw + (size_t)gid * SUMH + HOFF[l];

    __shared__ float sw[128];
    __shared__ float sbl[128];
    __shared__ float sH[128];
    const unsigned FM = 0xffffffffu;

    float u[4], ex[4];
    float m = -1e30f;
    for (int j = 0; j < E; j++) {
        int k = j * 32 + lane;
        u[j] = (k < n - 1) ? uw[k] : -1e30f;
        m = fmaxf(m, u[j]);
    }
    for (int o = 16; o; o >>= 1) m = fmaxf(m, __shfl_xor_sync(FM, m, o));

    float s = 0.f;
    for (int j = 0; j < E; j++) {
        int k = j * 32 + lane;
        ex[j] = (k < n - 1) ? expf(u[j] - m) : 0.f;
        s += ex[j];
    }
    for (int o = 16; o; o >>= 1) s += __shfl_xor_sync(FM, s, o);
    float inv = 1.f / s;

    // inclusive cumsum over k = j*32 + lane ordering
    float base = 0.f;
    for (int j = 0; j < E; j++) {
        int k = j * 32 + lane;
        float v = ex[j] * inv;            // w_k (0 for k == n-1 slot)
        float t = v;
        for (int o = 1; o < 32; o <<= 1) {
            float q = __shfl_up_sync(FM, t, o);
            if (lane >= o) t += q;
        }
        t += base;
        base = __shfl_sync(FM, t, 31);
        if (k < n - 1) { sw[k] = v; sbl[k + 1] = t; }
    }
    __syncwarp();
    if (lane == 0) { sbl[0] = 0.f; sbl[n - 1] = 1.0f; }  // ref forces last cumsum to 1
    __syncwarp();

    for (int j = 0; j < E; j++) {
        int k = j * 32 + lane;
        sH[k] = expf(uh[k]);
    }
    __syncwarp();

    float*  Aout = g_A   + AOFF[l] + g * n;
    float4* bin  = g_bin + BOFF[l] + g * (n - 1);
    for (int j = 0; j < E; j++) {
        int k = j * 32 + lane;
        float wkm1 = (k >= 1)     ? sw[k - 1] : 0.f;
        float wk   = (k < n - 1)  ? sw[k]     : 0.f;
        float c = 0.5f * (wkm1 + wk);
        Aout[k] = sH[k] * c;
        if (k < n - 1) bin[k] = make_float4(sH[k], sH[k + 1], sw[k], sbl[k]);
    }
    int ng = n >> 2;
    if (lane < ng) {
        int mg = lane;
        g_blg[GOFF[l] + g * ng + mg] = sbl[4 * mg];
        g_fbl[GOFF[l] + g * ng + mg] =
            make_float4(sbl[4 * mg], sbl[4 * mg + 1], sbl[4 * mg + 2], sbl[4 * mg + 3]);
    }
}

// ---------------------------------------------------------------------------
// Main: 8 lanes per point, 4 points per warp.
// Phase 1 (x-independent): load + exp + granule sums + full-area butterfly
// for ALL THREE layers, with every load in flight together.
// Phase 2 (x-dependent, serial): register-resident coarse bin search + masked
// partial + epilogue per layer.
// ---------------------------------------------------------------------------
template <int N>
__device__ __forceinline__ void layer_prefetch(
    int g, int sl,
    const float* __restrict__ dptr,
    const float* __restrict__ Abase,
    const float* __restrict__ blgbase,
    float* gs, float* blgr, float& full)
{
    constexpr int Gn = N / 32;
    constexpr int NG = N / 4;
    constexpr unsigned FM = 0xffffffffu;

    const float4* Av  = reinterpret_cast<const float4*>(Abase + g * N);
    const float4* Dv  = reinterpret_cast<const float4*>(dptr);
    const float*  blg = blgbase + g * NG;

#pragma unroll
    for (int j = 0; j < Gn; j++) {
        int mg = j * 8 + sl;
        float4 a = __ldg(Av + mg);
        float4 d = __ldg(Dv + mg);
        blgr[j]  = __ldg(blg + mg);
        float t01 = a.x * __expf(d.x) + a.y * __expf(d.y);
        float t23 = a.z * __expf(d.z) + a.w * __expf(d.w);
        gs[j] = t01 + t23;
    }
    full = gs[0];
#pragma unroll
    for (int j = 1; j < Gn; j++) full += gs[j];
#pragma unroll
    for (int o = 4; o; o >>= 1) full += __shfl_xor_sync(FM, full, o);
}

template <int N>
__device__ __forceinline__ void layer_finish(
    float& x, float& lad, int g, int sl,
    const float* __restrict__ dptr,
    const float* __restrict__ Abase,
    const float4* __restrict__ fblbase,
    const float4* __restrict__ binbase,
    const float* gs, const float* blgr, float full)
{
    constexpr int Gn = N / 32;
    constexpr int NG = N / 4;
    constexpr unsigned FM = 0xffffffffu;

    const float4* Av = reinterpret_cast<const float4*>(Abase + g * N);
    const float4* Dv = reinterpret_cast<const float4*>(dptr);

    // coarse search against register-resident granule boundaries
    int cntg = 0;
#pragma unroll
    for (int j = 0; j < Gn; j++) cntg += (x >= blgr[j]);
#pragma unroll
    for (int o = 4; o; o >>= 1) cntg += __shfl_xor_sync(FM, cntg, o);
    int gidx = cntg - 1;                 // cntg >= 1 since blg[0] = 0 <= x

    // partial cdf: granules strictly before gidx
    float part = 0.f;
#pragma unroll
    for (int j = 0; j < Gn; j++) {
        if (j * 8 + sl < gidx) part += gs[j];
    }
#pragma unroll
    for (int o = 4; o; o >>= 1) part += __shfl_xor_sync(FM, part, o);

    // fine refinement within granule (uniform per segment)
    float4 f = __ldg(fblbase + g * NG + gidx);
    int r = (x >= f.y) + (x >= f.z) + (x >= f.w);
    int kb0 = gidx * 4;
    int b = kb0 + r;
    if (b > N - 2) { b = N - 2; r = b - kb0; }

    // recompute b-granule terms from L1-hot lines (uniform per segment)
    float4 a = __ldg(Av + gidx);
    float4 d = __ldg(Dv + gidx);
    float e0 = __expf(d.x), e1 = __expf(d.y), e2 = __expf(d.z), e3 = __expf(d.w);
    part += a.x * e0;                    // k = kb0 <= b always
    if (r >= 1) part += a.y * e1;
    if (r >= 2) part += a.z * e2;
    if (r >= 3) part += a.w * e3;

    // exp(delta) at bins b and b+1
    float edb  = (r < 2) ? (r ? e1 : e0) : ((r == 3) ? e3 : e2);
    float edb1;
    if (r < 3) edb1 = (r == 0) ? e1 : ((r == 1) ? e2 : e3);
    else       edb1 = __expf(__ldg(dptr + b + 1));   // r==3 => b+1 <= N-1

    float4 sc = __ldg(binbase + g * (N - 1) + b);    // {H_b, H_{b+1}, w_b, bl_b}
    float ra  = __fdividef(1.f, full);
    float eb  = sc.x * edb;
    float eb1 = sc.y * edb1;
    float wb  = sc.z;
    float blb = sc.w;

    float in_cdf = (part - 0.5f * eb * wb) * ra;
    float hl = eb * ra;
    float hr = eb1 * ra;
    float alpha = __fdividef(x - blb, wb);
    float dhh = hr - hl;
    float out = fmaf(fmaf(0.5f * dhh * wb, alpha, hl * wb), alpha, in_cdf);
    out = fminf(fmaxf(out, 0.f), 1.f);
    lad += __logf(fmaf(alpha, dhh, hl));
    x = out;
}

__global__ __launch_bounds__(256, 3) void spline_main(
    const float* __restrict__ xin,
    const float* __restrict__ delta,
    const int* __restrict__ lgi,
    float* __restrict__ out,
    int n_points)
{
    int warp = (blockIdx.x * blockDim.x + threadIdx.x) >> 5;
    int lane = threadIdx.x & 31;
    int seg  = lane >> 3;        // 0..3 : point within warp
    int sl   = lane & 7;         // 0..7 : lane within point

    int p = warp * 4 + seg;
    int nwarps = (n_points + 3) >> 2;
    if (warp >= nwarps) return;              // whole warp exits together
    int pc = min(p, n_points - 1);           // clamp: keep all lanes converged

    float x = __ldg(xin + pc);
    int g = __ldg(lgi + pc);
    float lad = 0.f;
    const float* dptr = delta + (size_t)pc * SUMH;

    // ---- Phase 1: all x-independent loads + math for all three layers ----
    float gs0[4], bl0[4], f0;
    float gs1[2], bl1[2], f1;
    float gs2[1], bl2[1], f2;
    layer_prefetch<128>(g, sl, dptr,       g_A,              g_blg,             gs0, bl0, f0);
    layer_prefetch<64> (g, sl, dptr + 128, g_A + NGOI * 128, g_blg + NGOI * 32, gs1, bl1, f1);
    layer_prefetch<32> (g, sl, dptr + 192, g_A + NGOI * 192, g_blg + NGOI * 48, gs2, bl2, f2);

    // ---- Phase 2: serial x-dependent finish ----
    layer_finish<128>(x, lad, g, sl, dptr,       g_A,              g_fbl,             g_bin,              gs0, bl0, f0);
    layer_finish<64> (x, lad, g, sl, dptr + 128, g_A + NGOI * 128, g_fbl + NGOI * 32, g_bin + NGOI * 127, gs1, bl1, f1);
    layer_finish<32> (x, lad, g, sl, dptr + 192, g_A + NGOI * 192, g_fbl + NGOI * 48, g_bin + NGOI * 190, gs2, bl2, f2);

    if (p < n_points) {
        if (sl == 0) out[p] = x;
        if (sl == 1) out[n_points + p] = lad;
    }
}

extern "C" void kernel_launch(void* const* d_in, const int* in_sizes, int n_in,
                              void* d_out, int out_size)
{
    const float* x     = (const float*)d_in[0];
    const float* delta = (const float*)d_in[1];
    const float* hw    = (const float*)d_in[2];
    const float* ww    = (const float*)d_in[3];
    const int*   goi   = (const int*)d_in[4];
    const int*   lgi   = (const int*)d_in[5];
    float* out = (float*)d_out;
    int n = in_sizes[0];

    dim3 pg(NGOI, 3);
    precompute_kernel<<<pg, 32>>>(hw, ww, goi);

    int nwarps = (n + 3) / 4;                 // 4 points per warp
    int blocks = (nwarps * 32 + 255) / 256;
    spline_main<<<blocks, 256>>>(x, delta, lgi, out, n);
}

// round 10
// speedup vs baseline: 1.3513x; 1.3513x over previous
#include <cuda_runtime.h>
#include <cuda_bf16.h>
#include <math.h>

#define NGOI 500
#define SUMH 224
#define SUMW 221
#define SUMG 56   // SUMH/4 granules

// Gene-level precomputed tables (per layer blocks).
// g_A[k]   = A_k = H_k * c_k                      (length n per gene)
// g_blg[m] = bl[4m]  granule boundary             (length n/4 per gene)
// g_fbl[m] = {bl[4m],bl[4m+1],bl[4m+2],bl[4m+3]}  (length n/4 per gene)
// g_bin[b] = {H_b, H_{b+1}, w_b, bl_b}            (length n-1 per gene)
__device__ __align__(16) float  g_A[NGOI * SUMH];     // 448 KB
__device__ __align__(16) float  g_blg[NGOI * SUMG];   // 112 KB
__device__ __align__(16) float4 g_fbl[NGOI * SUMG];   // 448 KB
__device__ __align__(16) float4 g_bin[NGOI * SUMW];   // 1.77 MB

// ---------------------------------------------------------------------------
// Precompute: one warp per (gene, layer), 8 warps per block.
// softmax(widths) -> w, cumsum -> bl, H = exp(uh), c_k = 0.5*(w_{k-1}+w_k).
// ---------------------------------------------------------------------------
__global__ __launch_bounds__(256) void precompute_kernel(
    const float* __restrict__ hw,
    const float* __restrict__ ww,
    const int* __restrict__ goi)
{
    const int NB[3]   = {128, 64, 32};
    const int WOFF[3] = {0, 127, 190};
    const int HOFF[3] = {0, 128, 192};
    const int AOFF[3] = {0, NGOI * 128, NGOI * 192};
    const int GOFF[3] = {0, NGOI * 32,  NGOI * 48};
    const int BOFF[3] = {0, NGOI * 127, NGOI * 190};

    int gw = (blockIdx.x * blockDim.x + threadIdx.x) >> 5;   // global warp id
    if (gw >= NGOI * 3) return;
    int g = gw % NGOI;
    int l = gw / NGOI;
    int wslot = (threadIdx.x >> 5);
    int lane = threadIdx.x & 31;
    int n = NB[l];
    int E = n >> 5;
    int gid = goi[g];
    const float* uw = ww + (size_t)gid * SUMW + WOFF[l];
    const float* uh = hw + (size_t)gid * SUMH + HOFF[l];

    __shared__ float sw[8][128];
    __shared__ float sbl[8][128];
    __shared__ float sH[8][128];
    float* swp  = sw[wslot];
    float* sblp = sbl[wslot];
    float* sHp  = sH[wslot];
    const unsigned FM = 0xffffffffu;

    float u[4], ex[4];
    float m = -1e30f;
    for (int j = 0; j < E; j++) {
        int k = j * 32 + lane;
        u[j] = (k < n - 1) ? uw[k] : -1e30f;
        m = fmaxf(m, u[j]);
    }
    for (int o = 16; o; o >>= 1) m = fmaxf(m, __shfl_xor_sync(FM, m, o));

    float s = 0.f;
    for (int j = 0; j < E; j++) {
        int k = j * 32 + lane;
        ex[j] = (k < n - 1) ? expf(u[j] - m) : 0.f;
        s += ex[j];
    }
    for (int o = 16; o; o >>= 1) s += __shfl_xor_sync(FM, s, o);
    float inv = 1.f / s;

    // inclusive cumsum over k = j*32 + lane ordering
    float base = 0.f;
    for (int j = 0; j < E; j++) {
        int k = j * 32 + lane;
        float v = ex[j] * inv;            // w_k (0 for k == n-1 slot)
        float t = v;
        for (int o = 1; o < 32; o <<= 1) {
            float q = __shfl_up_sync(FM, t, o);
            if (lane >= o) t += q;
        }
        t += base;
        base = __shfl_sync(FM, t, 31);
        if (k < n - 1) { swp[k] = v; sblp[k + 1] = t; }
    }
    __syncwarp();
    if (lane == 0) { sblp[0] = 0.f; sblp[n - 1] = 1.0f; }  // ref forces last cumsum to 1
    __syncwarp();

    for (int j = 0; j < E; j++) {
        int k = j * 32 + lane;
        sHp[k] = expf(uh[k]);
    }
    __syncwarp();

    float*  Aout = g_A   + AOFF[l] + g * n;
    float4* bin  = g_bin + BOFF[l] + g * (n - 1);
    for (int j = 0; j < E; j++) {
        int k = j * 32 + lane;
        float wkm1 = (k >= 1)     ? swp[k - 1] : 0.f;
        float wk   = (k < n - 1)  ? swp[k]     : 0.f;
        float c = 0.5f * (wkm1 + wk);
        Aout[k] = sHp[k] * c;
        if (k < n - 1) bin[k] = make_float4(sHp[k], sHp[k + 1], swp[k], sblp[k]);
    }
    int ng = n >> 2;
    if (lane < ng) {
        int mg = lane;
        g_blg[GOFF[l] + g * ng + mg] = sblp[4 * mg];
        g_fbl[GOFF[l] + g * ng + mg] =
            make_float4(sblp[4 * mg], sblp[4 * mg + 1], sblp[4 * mg + 2], sblp[4 * mg + 3]);
    }
}

// ---------------------------------------------------------------------------
// Main: 8 lanes per point, 4 points per warp. Granule m = j*8 + sl covers
// bins [4m, 4m+4). Main loop: A float4 + delta float4 + granule-boundary bl
// scalar per granule. Two-level bin search: granule count in main loop,
// fine refinement (uniform float4) in epilogue. Whole delta row is
// L2-prefetched at warp entry (register-free latency hiding for layers 2/3).
// ---------------------------------------------------------------------------
template <int N>
__device__ __forceinline__ void spline_layer(
    float& x, float& lad, int g, int sl,
    const float* __restrict__ dptr,
    const float* __restrict__ Abase,
    const float* __restrict__ blgbase,
    const float4* __restrict__ fblbase,
    const float4* __restrict__ binbase)
{
    constexpr int Gn = N / 32;           // granules per lane
    constexpr int NG = N / 4;            // granules per layer
    constexpr unsigned FM = 0xffffffffu;

    const float4* Av  = reinterpret_cast<const float4*>(Abase + g * N);
    const float4* Dv  = reinterpret_cast<const float4*>(dptr);
    const float*  blg = blgbase + g * NG;

    float gs[Gn];
    int cntg = 0;
#pragma unroll
    for (int j = 0; j < Gn; j++) {
        int mg = j * 8 + sl;
        float4 a = __ldg(Av + mg);
        float4 d = __ldg(Dv + mg);
        float bg = __ldg(blg + mg);
        float t01 = a.x * __expf(d.x) + a.y * __expf(d.y);
        float t23 = a.z * __expf(d.z) + a.w * __expf(d.w);
        gs[j] = t01 + t23;
        cntg += (x >= bg);
    }

    float full = gs[0];
#pragma unroll
    for (int j = 1; j < Gn; j++) full += gs[j];

    // segmented (width-8) butterfly: granule count + full area
#pragma unroll
    for (int o = 4; o; o >>= 1) {
        cntg += __shfl_xor_sync(FM, cntg, o);
        full += __shfl_xor_sync(FM, full, o);
    }
    int gidx = cntg - 1;                 // cntg >= 1 since blg[0] = 0 <= x

    // partial cdf: granules strictly before gidx
    float part = 0.f;
#pragma unroll
    for (int j = 0; j < Gn; j++) {
        if (j * 8 + sl < gidx) part += gs[j];
    }
#pragma unroll
    for (int o = 4; o; o >>= 1) part += __shfl_xor_sync(FM, part, o);

    // fine refinement within granule (uniform per segment)
    float4 f = __ldg(fblbase + g * NG + gidx);
    int r = (x >= f.y) + (x >= f.z) + (x >= f.w);
    int kb0 = gidx * 4;
    int b = kb0 + r;
    if (b > N - 2) { b = N - 2; r = b - kb0; }

    // recompute b-granule terms from L1-hot lines (uniform per segment)
    float4 a = __ldg(Av + gidx);
    float4 d = __ldg(Dv + gidx);
    float e0 = __expf(d.x), e1 = __expf(d.y), e2 = __expf(d.z), e3 = __expf(d.w);
    part += a.x * e0;                    // k = kb0 <= b always
    if (r >= 1) part += a.y * e1;
    if (r >= 2) part += a.z * e2;
    if (r >= 3) part += a.w * e3;

    // exp(delta) at bins b and b+1
    float edb  = (r < 2) ? (r ? e1 : e0) : ((r == 3) ? e3 : e2);
    float edb1;
    if (r < 3) edb1 = (r == 0) ? e1 : ((r == 1) ? e2 : e3);
    else       edb1 = __expf(__ldg(dptr + b + 1));   // r==3 => b+1 <= N-1

    float4 sc = __ldg(binbase + g * (N - 1) + b);    // {H_b, H_{b+1}, w_b, bl_b}
    float ra  = __fdividef(1.f, full);
    float eb  = sc.x * edb;
    float eb1 = sc.y * edb1;
    float wb  = sc.z;
    float blb = sc.w;

    float in_cdf = (part - 0.5f * eb * wb) * ra;
    float hl = eb * ra;
    float hr = eb1 * ra;
    float alpha = __fdividef(x - blb, wb);
    float dhh = hr - hl;
    float out = fmaf(fmaf(0.5f * dhh * wb, alpha, hl * wb), alpha, in_cdf);
    out = fminf(fmaxf(out, 0.f), 1.f);
    lad += __logf(fmaf(alpha, dhh, hl));
    x = out;
}

__global__ __launch_bounds__(256) void spline_main(
    const float* __restrict__ xin,
    const float* __restrict__ delta,
    const int* __restrict__ lgi,
    float* __restrict__ out,
    int n_points)
{
    int warp = (blockIdx.x * blockDim.x + threadIdx.x) >> 5;
    int lane = threadIdx.x & 31;
    int seg  = lane >> 3;        // 0..3 : point within warp
    int sl   = lane & 7;         // 0..7 : lane within point

    int p = warp * 4 + seg;
    int nwarps = (n_points + 3) >> 2;
    if (warp >= nwarps) return;              // whole warp exits together
    int pc = min(p, n_points - 1);           // clamp: keep all lanes converged

    const float* dptr = delta + (size_t)pc * SUMH;

    // L2-prefetch the full 896B delta row: 8 lanes x 112B stride touches
    // every 128B line of the row. One warp instruction, zero registers.
    asm volatile("prefetch.global.L2 [%0];"
                 :: "l"(reinterpret_cast<const char*>(dptr) + sl * 112));

    float x = __ldg(xin + pc);
    int g = __ldg(lgi + pc);
    float lad = 0.f;

    spline_layer<128>(x, lad, g, sl, dptr,
                      g_A,              g_blg,            g_fbl,            g_bin);
    spline_layer<64> (x, lad, g, sl, dptr + 128,
                      g_A + NGOI * 128, g_blg + NGOI * 32, g_fbl + NGOI * 32, g_bin + NGOI * 127);
    spline_layer<32> (x, lad, g, sl, dptr + 192,
                      g_A + NGOI * 192, g_blg + NGOI * 48, g_fbl + NGOI * 48, g_bin + NGOI * 190);

    if (p < n_points) {
        if (sl == 0) out[p] = x;
        if (sl == 1) out[n_points + p] = lad;
    }
}

extern "C" void kernel_launch(void* const* d_in, const int* in_sizes, int n_in,
                              void* d_out, int out_size)
{
    const float* x     = (const float*)d_in[0];
    const float* delta = (const float*)d_in[1];
    const float* hw    = (const float*)d_in[2];
    const float* ww    = (const float*)d_in[3];
    const int*   goi   = (const int*)d_in[4];
    const int*   lgi   = (const int*)d_in[5];
    float* out = (float*)d_out;
    int n = in_sizes[0];

    int pwarps = NGOI * 3;
    precompute_kernel<<<(pwarps * 32 + 255) / 256, 256>>>(hw, ww, goi);

    int nwarps = (n + 3) / 4;                 // 4 points per warp
    int blocks = (nwarps * 32 + 255) / 256;
    spline_main<<<blocks, 256>>>(x, delta, lgi, out, n);
}